// round 6
// baseline (speedup 1.0000x reference)
#include <cuda_runtime.h>
#include <cuda_bf16.h>

#define IMG_H 1024
#define IMG_W 1024
#define N_PLANES 24   // B*C = 8*3
#define RES_SCALE 0.2f

__device__ __forceinline__ float med3f(float a, float b, float c) {
    return fmaxf(fminf(a, b), fminf(fmaxf(a, b), c));
}

// Load one image row segment (cols c0-1 .. c0+8) into v[10].
// Halo via intra-warp shuffle; lanes 0/31 use predicated scalar loads.
__device__ __forceinline__ void load_row(const float* __restrict__ row, bool valid,
                                         int c0, int lane, float* v) {
    const float4 z4 = make_float4(0.f, 0.f, 0.f, 0.f);
    float4 q0 = valid ? *(const float4*)(row + c0)     : z4;
    float4 q1 = valid ? *(const float4*)(row + c0 + 4) : z4;
    const bool pL = (lane == 0);
    const bool pR = (lane == 31);
    float hl = (pL & (c0 > 0) & valid)           ? row[c0 - 1] : 0.f;
    float hr = (pR & (c0 + 8 < IMG_W) & valid)   ? row[c0 + 8] : 0.f;
    const unsigned fm = 0xffffffffu;
    float sl = __shfl_up_sync(fm, q1.w, 1);
    float sr = __shfl_down_sync(fm, q0.x, 1);
    v[0] = pL ? hl : sl;
    v[1] = q0.x; v[2] = q0.y; v[3] = q0.z; v[4] = q0.w;
    v[5] = q1.x; v[6] = q1.y; v[7] = q1.z; v[8] = q1.w;
    v[9] = pR ? hr : sr;
}

// Column sort of {outer, pair(s,t)} for one window row.
__device__ __forceinline__ void colsort(const float* s, const float* t, const float* o,
                                        float* lo, float* mi, float* hi) {
#pragma unroll
    for (int j = 0; j < 10; j++) {
        lo[j] = fminf(o[j], s[j]);
        hi[j] = fmaxf(o[j], t[j]);
        mi[j] = fmaxf(s[j], fminf(o[j], t[j]));
    }
}

// Horizontal combine with shared pair sorts; writes 8 residual-blended pixels.
__device__ __forceinline__ void combine_row(const float* lo, const float* mi, const float* hi,
                                            const float* xr, float* __restrict__ ob) {
    float res[8];
#pragma unroll
    for (int pi = 0; pi < 4; pi++) {
        const int i = 2 * pi + 1;
        const float pmx = fmaxf(lo[i], lo[i + 1]);
        const float pmn = fminf(hi[i], hi[i + 1]);
        const float psn = fminf(mi[i], mi[i + 1]);
        const float psx = fmaxf(mi[i], mi[i + 1]);
        {
            const float M  = fmaxf(lo[i - 1], pmx);
            const float N  = fminf(hi[i - 1], pmn);
            const float md = fmaxf(psn, fminf(psx, mi[i - 1]));
            const float m  = med3f(M, md, N);
            const float xv = xr[i];
            res[i - 1] = xv + RES_SCALE * (m - xv);
        }
        {
            const float M  = fmaxf(pmx, lo[i + 2]);
            const float N  = fminf(pmn, hi[i + 2]);
            const float md = fmaxf(psn, fminf(psx, mi[i + 2]));
            const float m  = med3f(M, md, N);
            const float xv = xr[i + 1];
            res[i] = xv + RES_SCALE * (m - xv);
        }
    }
    __stcs((float4*)(ob),     make_float4(res[0], res[1], res[2], res[3]));
    __stcs((float4*)(ob + 4), make_float4(res[4], res[5], res[6], res[7]));
}

__global__ __launch_bounds__(128)
void MedianBlur_30966714204228_kernel(const float* __restrict__ x,
                                      float* __restrict__ out) {
    const int r     = blockIdx.x << 2;   // top output row of the quad (0,4,..,1020)
    const int plane = blockIdx.y;        // 0..23
    const int tid   = threadIdx.x;       // 0..127
    const int lane  = tid & 31;
    const int c0    = tid << 3;          // 8 pixels per thread per row

    const float* p    = x + (size_t)plane * (IMG_H * IMG_W);
    const float* rowB = p + (size_t)r * IMG_W;       // row r
    const bool hasA = (r > 0);
    const bool hasF = (r + 4 < IMG_H);

    // 6 input rows: A=r-1, B=r, C=r+1, D=r+2, E=r+3, F=r+4
    float A[10], B[10], C[10], D[10], E[10], F[10];
    load_row(rowB - IMG_W,     hasA, c0, lane, A);
    load_row(rowB,             true, c0, lane, B);
    load_row(rowB + IMG_W,     true, c0, lane, C);
    load_row(rowB + 2 * IMG_W, true, c0, lane, D);
    load_row(rowB + 3 * IMG_W, true, c0, lane, E);
    load_row(rowB + 4 * IMG_W, hasF, c0, lane, F);

    // Shared vertical pair sorts: (B,C) serves windows at rows B,C; (D,E) serves D,E.
    float s1[10], t1[10], s2[10], t2[10];
#pragma unroll
    for (int j = 0; j < 10; j++) {
        s1[j] = fminf(B[j], C[j]);
        t1[j] = fmaxf(B[j], C[j]);
        s2[j] = fminf(D[j], E[j]);
        t2[j] = fmaxf(D[j], E[j]);
    }

    float* ob = out + (size_t)plane * (IMG_H * IMG_W) + (size_t)r * IMG_W + c0;
    float lo[10], mi[10], hi[10];

    // window row B: {A, B, C}
    colsort(s1, t1, A, lo, mi, hi);
    combine_row(lo, mi, hi, B, ob);
    // window row C: {B, C, D}
    colsort(s1, t1, D, lo, mi, hi);
    combine_row(lo, mi, hi, C, ob + IMG_W);
    // window row D: {C, D, E}
    colsort(s2, t2, C, lo, mi, hi);
    combine_row(lo, mi, hi, D, ob + 2 * IMG_W);
    // window row E: {D, E, F}
    colsort(s2, t2, F, lo, mi, hi);
    combine_row(lo, mi, hi, E, ob + 3 * IMG_W);
}

extern "C" void kernel_launch(void* const* d_in, const int* in_sizes, int n_in,
                              void* d_out, int out_size) {
    const float* x = (const float*)d_in[0];
    float* o = (float*)d_out;
    dim3 grid(IMG_H / 4, N_PLANES);
    MedianBlur_30966714204228_kernel<<<grid, 128>>>(x, o);
}

// round 7
// speedup vs baseline: 1.1366x; 1.1366x over previous
#include <cuda_runtime.h>
#include <cuda_fp16.h>

#define IMG_H 1024
#define IMG_W 1024
#define N_PLANES 24   // B*C = 8*3
#define RES_SCALE 0.2f

__device__ __forceinline__ __half2 h2mn(__half2 a, __half2 b) { return __hmin2(a, b); }
__device__ __forceinline__ __half2 h2mx(__half2 a, __half2 b) { return __hmax2(a, b); }

// Load one image row segment (cols c0-1 .. c0+8) into v[10] (fp32).
// Halo via intra-warp shuffle; lanes 0/31 use predicated scalar loads.
__device__ __forceinline__ void load_row(const float* __restrict__ row, bool valid,
                                         int c0, int lane, float* v) {
    const float4 z4 = make_float4(0.f, 0.f, 0.f, 0.f);
    float4 q0 = valid ? *(const float4*)(row + c0)     : z4;
    float4 q1 = valid ? *(const float4*)(row + c0 + 4) : z4;
    const bool pL = (lane == 0);
    const bool pR = (lane == 31);
    float hl = (pL & (c0 > 0) & valid)         ? row[c0 - 1] : 0.f;
    float hr = (pR & (c0 + 8 < IMG_W) & valid) ? row[c0 + 8] : 0.f;
    const unsigned fm = 0xffffffffu;
    float sl = __shfl_up_sync(fm, q1.w, 1);
    float sr = __shfl_down_sync(fm, q0.x, 1);
    v[0] = pL ? hl : sl;
    v[1] = q0.x; v[2] = q0.y; v[3] = q0.z; v[4] = q0.w;
    v[5] = q1.x; v[6] = q1.y; v[7] = q1.z; v[8] = q1.w;
    v[9] = pR ? hr : sr;
}

// Packed column sort: windows (x-half, y-half) share pre-sorted vertical pair (s,t).
__device__ __forceinline__ void colsort_pk(const __half2* s, const __half2* t, const __half2* o,
                                           __half2* lo, __half2* mi, __half2* hi) {
#pragma unroll
    for (int j = 0; j < 10; j++) {
        lo[j] = h2mn(o[j], s[j]);
        hi[j] = h2mx(o[j], t[j]);
        mi[j] = h2mx(s[j], h2mn(o[j], t[j]));
    }
}

// Packed horizontal combine for 2 window-rows; residual in fp32 with exact x;
// streams 2 output rows (centers xr0 -> ob0 and xr1 -> ob1).
__device__ __forceinline__ void combine_pk(const __half2* lo, const __half2* mi, const __half2* hi,
                                           const float* xr0, const float* xr1,
                                           float* __restrict__ ob0, float* __restrict__ ob1) {
    float r0[8], r1[8];
#pragma unroll
    for (int pi = 0; pi < 4; pi++) {
        const int i = 2 * pi + 1;
        const __half2 pmx = h2mx(lo[i], lo[i + 1]);
        const __half2 pmn = h2mn(hi[i], hi[i + 1]);
        const __half2 psn = h2mn(mi[i], mi[i + 1]);
        const __half2 psx = h2mx(mi[i], mi[i + 1]);
        {   // window i-1 : pair + column i-1
            const __half2 M  = h2mx(lo[i - 1], pmx);
            const __half2 N  = h2mn(hi[i - 1], pmn);
            const __half2 md = h2mx(psn, h2mn(psx, mi[i - 1]));
            const __half2 mn = h2mn(M, md);
            const __half2 mx = h2mx(M, md);
            const __half2 m  = h2mx(mn, h2mn(mx, N));
            const float m0 = __low2float(m), m1 = __high2float(m);
            r0[i - 1] = xr0[i] + RES_SCALE * (m0 - xr0[i]);
            r1[i - 1] = xr1[i] + RES_SCALE * (m1 - xr1[i]);
        }
        {   // window i : pair + column i+2
            const __half2 M  = h2mx(pmx, lo[i + 2]);
            const __half2 N  = h2mn(pmn, hi[i + 2]);
            const __half2 md = h2mx(psn, h2mn(psx, mi[i + 2]));
            const __half2 mn = h2mn(M, md);
            const __half2 mx = h2mx(M, md);
            const __half2 m  = h2mx(mn, h2mn(mx, N));
            const float m0 = __low2float(m), m1 = __high2float(m);
            r0[i] = xr0[i + 1] + RES_SCALE * (m0 - xr0[i + 1]);
            r1[i] = xr1[i + 1] + RES_SCALE * (m1 - xr1[i + 1]);
        }
    }
    __stcs((float4*)(ob0),     make_float4(r0[0], r0[1], r0[2], r0[3]));
    __stcs((float4*)(ob0 + 4), make_float4(r0[4], r0[5], r0[6], r0[7]));
    __stcs((float4*)(ob1),     make_float4(r1[0], r1[1], r1[2], r1[3]));
    __stcs((float4*)(ob1 + 4), make_float4(r1[4], r1[5], r1[6], r1[7]));
}

__global__ __launch_bounds__(128)
void MedianBlur_30966714204228_kernel(const float* __restrict__ x,
                                      float* __restrict__ out) {
    const int r     = blockIdx.x << 2;   // top output row of the quad
    const int plane = blockIdx.y;        // 0..23
    const int tid   = threadIdx.x;       // 0..127
    const int lane  = tid & 31;
    const int c0    = tid << 3;          // 8 pixels per thread per row

    const float* p    = x + (size_t)plane * (IMG_H * IMG_W);
    const float* rowB = p + (size_t)r * IMG_W;
    const bool hasA = (r > 0);
    const bool hasF = (r + 4 < IMG_H);

    // 6 input rows (fp32): A=r-1 .. F=r+4
    float A[10], B[10], C[10], D[10], E[10], F[10];
    load_row(rowB - IMG_W,     hasA, c0, lane, A);
    load_row(rowB,             true, c0, lane, B);
    load_row(rowB + IMG_W,     true, c0, lane, C);
    load_row(rowB + 2 * IMG_W, true, c0, lane, D);
    load_row(rowB + 3 * IMG_W, true, c0, lane, E);
    load_row(rowB + 4 * IMG_W, hasF, c0, lane, F);

    // Pack: x-half serves window-rows (B,C), y-half serves (D,E).
    //   u=(B,D), v=(C,E)  -> shared vertical pair sort for ALL 4 windows
    //   op=(A,C): outer rows of windows (B,D);  oq=(D,F): outer rows of windows (C,E)
    __half2 u[10], v[10], op_[10], oq[10];
#pragma unroll
    for (int j = 0; j < 10; j++) {
        u[j]   = __floats2half2_rn(B[j], D[j]);
        v[j]   = __floats2half2_rn(C[j], E[j]);
        op_[j] = __floats2half2_rn(A[j], C[j]);
        oq[j]  = __floats2half2_rn(D[j], F[j]);
    }
    __half2 s[10], t[10];
#pragma unroll
    for (int j = 0; j < 10; j++) {
        s[j] = h2mn(u[j], v[j]);
        t[j] = h2mx(u[j], v[j]);
    }

    float* ob = out + (size_t)plane * (IMG_H * IMG_W) + (size_t)r * IMG_W + c0;
    __half2 lo[10], mi[10], hi[10];

    // windows at rows B (out r) and D (out r+2)
    colsort_pk(s, t, op_, lo, mi, hi);
    combine_pk(lo, mi, hi, B, D, ob, ob + 2 * IMG_W);

    // windows at rows C (out r+1) and E (out r+3)
    colsort_pk(s, t, oq, lo, mi, hi);
    combine_pk(lo, mi, hi, C, E, ob + IMG_W, ob + 3 * IMG_W);
}

extern "C" void kernel_launch(void* const* d_in, const int* in_sizes, int n_in,
                              void* d_out, int out_size) {
    const float* x = (const float*)d_in[0];
    float* o = (float*)d_out;
    dim3 grid(IMG_H / 4, N_PLANES);
    MedianBlur_30966714204228_kernel<<<grid, 128>>>(x, o);
}